// round 6
// baseline (speedup 1.0000x reference)
#include <cuda_runtime.h>
#include <cuda_bf16.h>
#include <stdint.h>

#define S_REAL   308
#define SP       320     // padded state count
#define E_DIM    126
#define T_LEN    4096
#define NBATCH   32
#define NIP      160     // SP/2 pair-words of alpha
#define SCAN_THREADS 640
#define KK       80      // i-pairs per h-slice (per thread, 1 j each)
#define KK_RES   64      // register-resident words
#define KK_STR   16      // streamed words (4 x LDG.128 per step, L1-hot)

// Scratch (device globals — no allocation in kernel_launch)
__device__ __nv_bfloat16 g_emis[(size_t)NBATCH * T_LEN * SP];   // 80 MB
__device__ uint32_t g_areg[160 * SP];       // A pair-words, thread-major, 200 KB
__device__ uint32_t g_astr[2 * 4 * SP * 4]; // streamed slice (kk 64..79), 40 KB

__device__ __forceinline__ __nv_bfloat162 u32_bf2(uint32_t v) {
    return *reinterpret_cast<__nv_bfloat162*>(&v);
}
__device__ __forceinline__ uint32_t bf2_u32(__nv_bfloat162 v) {
    return *reinterpret_cast<uint32_t*>(&v);
}

// ---------------------------------------------------------------------------
// Merged prep + emission GEMM.
// Blocks with (bx==0, by<80) first pack A into g_areg/g_astr (independent of
// the GEMM), then all blocks run the GEMM tile. 2 launches per call total so
// ncu -s 5 -c 1 lands on the scan kernel.
//
// g_areg[ip*320 + j]  = bf16x2( A[2ip][j], A[2ip+1][j] ), zero-padded.
// g_astr: for ip = h*80 + kk, kk>=64: c=(kk-64)>>2, s=(kk-64)&3 ->
//         word ((h*4+c)*320 + j)*4 + s   (so one uint4 = 4 consecutive kk).
// ---------------------------------------------------------------------------
__global__ void __launch_bounds__(256)
prep_gemm_kernel(const float* __restrict__ inp, const float* __restrict__ Bm,
                 const float* __restrict__ A) {
    const int tid = threadIdx.x;

    if (blockIdx.x == 0 && blockIdx.y < 80) {
        int gt = blockIdx.y * 256 + tid;
        for (int w = gt; w < 160 * SP; w += 80 * 256) {
            int ip = w / SP;
            int j  = w - ip * SP;
            int i0 = 2 * ip, i1 = i0 + 1;
            float a0 = (i0 < S_REAL && j < S_REAL) ? A[i0 * S_REAL + j] : 0.f;
            float a1 = (i1 < S_REAL && j < S_REAL) ? A[i1 * S_REAL + j] : 0.f;
            uint32_t word = bf2_u32(__floats2bfloat162_rn(a0, a1));
            g_areg[w] = word;
            int h = ip / 80, kk = ip - h * 80;
            if (kk >= KK_RES) {
                int c = (kk - KK_RES) >> 2, s = (kk - KK_RES) & 3;
                g_astr[(((h * 4 + c) * SP) + j) * 4 + s] = word;
            }
        }
    }

    // ---------------- GEMM part (all blocks) ----------------
    __shared__ uint32_t sAp[64][16];
    __shared__ uint32_t sBp[16][64];

    const int tx = tid & 15;
    const int ty = tid >> 4;
    const int n0 = blockIdx.x * 64;
    const int m0 = blockIdx.y * 64;

    float acc[4][4];
#pragma unroll
    for (int u = 0; u < 4; ++u)
#pragma unroll
        for (int v = 0; v < 4; ++v) acc[u][v] = 0.f;

    const __nv_bfloat162 zero2 = __floats2bfloat162_rn(0.f, 0.f);

    for (int k0 = 0; k0 < 128; k0 += 32) {
#pragma unroll
        for (int r = 0; r < 4; ++r) {
            int lin = tid + r * 256;
            int mm = lin >> 4, kp = lin & 15;
            int k = k0 + 2 * kp;
            __nv_bfloat162 w = zero2;
            if (k < E_DIM) {
                float2 f = *reinterpret_cast<const float2*>(
                    &inp[(size_t)(m0 + mm) * E_DIM + k]);
                w = __floats2bfloat162_rn(f.x, f.y);
            }
            sAp[mm][kp] = bf2_u32(w);
        }
#pragma unroll
        for (int r = 0; r < 4; ++r) {
            int lin = tid + r * 256;
            int kp = lin >> 6, n = lin & 63;
            int k = k0 + 2 * kp;
            int nn = n0 + n;
            __nv_bfloat162 w = zero2;
            if (k < E_DIM && nn < S_REAL) {
                float2 f = *reinterpret_cast<const float2*>(
                    &Bm[(size_t)nn * E_DIM + k]);
                w = __floats2bfloat162_rn(f.x, f.y);
            }
            sBp[kp][n] = bf2_u32(w);
        }
        __syncthreads();

        __nv_bfloat162 acc2[4][4];
#pragma unroll
        for (int u = 0; u < 4; ++u)
#pragma unroll
            for (int v = 0; v < 4; ++v) acc2[u][v] = zero2;

#pragma unroll
        for (int kp = 0; kp < 16; ++kp) {
            uint4 bv = *reinterpret_cast<const uint4*>(&sBp[kp][tx * 4]);
            uint32_t a0 = sAp[ty * 4 + 0][kp];
            uint32_t a1 = sAp[ty * 4 + 1][kp];
            uint32_t a2 = sAp[ty * 4 + 2][kp];
            uint32_t a3 = sAp[ty * 4 + 3][kp];
            __nv_bfloat162 b0 = u32_bf2(bv.x), b1 = u32_bf2(bv.y);
            __nv_bfloat162 b2 = u32_bf2(bv.z), b3 = u32_bf2(bv.w);
            acc2[0][0] = __hfma2(u32_bf2(a0), b0, acc2[0][0]);
            acc2[0][1] = __hfma2(u32_bf2(a0), b1, acc2[0][1]);
            acc2[0][2] = __hfma2(u32_bf2(a0), b2, acc2[0][2]);
            acc2[0][3] = __hfma2(u32_bf2(a0), b3, acc2[0][3]);
            acc2[1][0] = __hfma2(u32_bf2(a1), b0, acc2[1][0]);
            acc2[1][1] = __hfma2(u32_bf2(a1), b1, acc2[1][1]);
            acc2[1][2] = __hfma2(u32_bf2(a1), b2, acc2[1][2]);
            acc2[1][3] = __hfma2(u32_bf2(a1), b3, acc2[1][3]);
            acc2[2][0] = __hfma2(u32_bf2(a2), b0, acc2[2][0]);
            acc2[2][1] = __hfma2(u32_bf2(a2), b1, acc2[2][1]);
            acc2[2][2] = __hfma2(u32_bf2(a2), b2, acc2[2][2]);
            acc2[2][3] = __hfma2(u32_bf2(a2), b3, acc2[2][3]);
            acc2[3][0] = __hfma2(u32_bf2(a3), b0, acc2[3][0]);
            acc2[3][1] = __hfma2(u32_bf2(a3), b1, acc2[3][1]);
            acc2[3][2] = __hfma2(u32_bf2(a3), b2, acc2[3][2]);
            acc2[3][3] = __hfma2(u32_bf2(a3), b3, acc2[3][3]);
        }
#pragma unroll
        for (int u = 0; u < 4; ++u)
#pragma unroll
            for (int v = 0; v < 4; ++v) {
                float2 p = __bfloat1622float2(acc2[u][v]);
                acc[u][v] += p.x + p.y;
            }
        __syncthreads();
    }
#pragma unroll
    for (int u = 0; u < 4; ++u) {
        int m = m0 + ty * 4 + u;
        size_t base = (size_t)m * SP + n0 + tx * 4;
#pragma unroll
        for (int v = 0; v < 4; v += 2) {
            __nv_bfloat162 p = __floats2bfloat162_rn(acc[u][v], acc[u][v + 1]);
            *reinterpret_cast<uint32_t*>(&g_emis[base + v]) = bf2_u32(p);
        }
    }
}

// ---------------------------------------------------------------------------
// Scan: one CTA per batch, 640 threads = 2 h-splits x 320 j (one j per thread).
// Thread (h, j) accumulates A[i][j]*alpha[i] over i-pairs h*80..h*80+79:
// 64 words register-resident, 16 streamed (4 coalesced LDG.128, L1-hot).
// Two 40-term bf16x2 accumulators, fp32 collapse. h=1 stores partial to smem,
// h=0 adds + multiplies by emission. Alpha double-buffered bf16x2 in smem,
// renormalize + log-accumulate every 8 steps (telescoped). 2 barriers/step.
// ---------------------------------------------------------------------------
__global__ void __launch_bounds__(SCAN_THREADS, 1)
scan_kernel(const float* __restrict__ Ivec, float* __restrict__ out) {
    __shared__ uint32_t s_alpha[2][NIP];   // bf16 alpha pairs, double-buffered
    __shared__ float    s_red[SP];         // h=1 partials
    __shared__ float    s_w[10];
    __shared__ float    s_inv;

    const int b   = blockIdx.x;
    const int tid = threadIdx.x;
    const int h   = tid >= SP ? 1 : 0;     // warps 0..9 -> h=0, 10..19 -> h=1
    const int j   = tid - h * SP;          // 0..319

    const __nv_bfloat16* erow = g_emis + (size_t)b * T_LEN * SP;

    // register-resident A words: kk = 0..63
    uint32_t rA[KK_RES];
    {
        const uint32_t* Ar = g_areg + (size_t)(h * KK) * SP + j;
#pragma unroll
        for (int k = 0; k < KK_RES; ++k) rA[k] = Ar[(size_t)k * SP];
    }
    const uint4* As = reinterpret_cast<const uint4*>(g_astr) + (h * 4) * SP + j;

    // t = 0: alpha0 = I * e0 (unnormalized) into buffer 1 (t=1 reads buf 1)
    if (tid < NIP) {
        int j0 = 2 * tid, j1 = j0 + 1;
        float e0 = __bfloat162float(erow[j0]);
        float e1 = __bfloat162float(erow[j1]);
        float w0 = (j0 < S_REAL) ? Ivec[j0] : 0.f;
        float w1 = (j1 < S_REAL) ? Ivec[j1] : 0.f;
        s_alpha[1][tid] = bf2_u32(__floats2bfloat162_rn(w0 * e0, w1 * e1));
    }
    __syncthreads();

    float ll = 0.f;
    float e_cur = 0.f;
    if (h == 0) e_cur = __bfloat162float(erow[(size_t)SP + j]);

    const __nv_bfloat162 zero2 = __floats2bfloat162_rn(0.f, 0.f);

    for (int t = 1; t < T_LEN; ++t) {
        const int cur = t & 1;
        float e_next = 0.f;
        if (h == 0 && t + 1 < T_LEN)
            e_next = __bfloat162float(erow[(size_t)(t + 1) * SP + j]);

        const uint4* al4 = reinterpret_cast<const uint4*>(s_alpha[cur]) + h * 20;

        __nv_bfloat162 accA = zero2, accB = zero2;

        // streamed A (kk 64..79): issue all 4 LDG.128 early (L1 hits)
        uint4 sb0 = As[0 * SP];
        uint4 sb1 = As[1 * SP];
        uint4 sb2 = As[2 * SP];
        uint4 sb3 = As[3 * SP];

        // resident part: kk 0..39 -> accA, 40..63 -> accB
#pragma unroll
        for (int g = 0; g < 16; ++g) {
            uint4 av = al4[g];
            const uint32_t* aw = reinterpret_cast<const uint32_t*>(&av);
#pragma unroll
            for (int s = 0; s < 4; ++s) {
                int kk = g * 4 + s;
                if (kk < 40)
                    accA = __hfma2(u32_bf2(rA[kk]), u32_bf2(aw[s]), accA);
                else
                    accB = __hfma2(u32_bf2(rA[kk]), u32_bf2(aw[s]), accB);
            }
        }
        // streamed part: kk 64..79 -> accB
#pragma unroll
        for (int c = 0; c < 4; ++c) {
            uint4 av = al4[16 + c];
            const uint32_t* aw = reinterpret_cast<const uint32_t*>(&av);
            uint4 w = (c == 0) ? sb0 : (c == 1) ? sb1 : (c == 2) ? sb2 : sb3;
            accB = __hfma2(u32_bf2(w.x), u32_bf2(aw[0]), accB);
            accB = __hfma2(u32_bf2(w.y), u32_bf2(aw[1]), accB);
            accB = __hfma2(u32_bf2(w.z), u32_bf2(aw[2]), accB);
            accB = __hfma2(u32_bf2(w.w), u32_bf2(aw[3]), accB);
        }

        float2 pa = __bfloat1622float2(accA);
        float2 pb = __bfloat1622float2(accB);
        float f = (pa.x + pa.y) + (pb.x + pb.y);

        if (h == 1) s_red[j] = f;
        __syncthreads();

        float o = 0.f;
        if (h == 0) o = (f + s_red[j]) * e_cur;

        if ((t & 7) == 7) {
            // cluster-free renorm: warp reduce over h=0, then 10-way combine
            if (h == 0) {
                float s = o;
#pragma unroll
                for (int off = 16; off > 0; off >>= 1)
                    s += __shfl_xor_sync(0xffffffffu, s, off);
                if ((tid & 31) == 0) s_w[tid >> 5] = s;
            }
            __syncthreads();
            if (tid == 0) {
                float z = 0.f;
#pragma unroll
                for (int k = 0; k < 10; ++k) z += s_w[k];
                ll += logf(z);
                s_inv = 1.0f / z;
            }
            __syncthreads();
            if (h == 0) o *= s_inv;
        }

        // pack adjacent-j pair and store next alpha buffer
        if (h == 0) {
            float op = __shfl_down_sync(0xffffffffu, o, 1);
            if ((j & 1) == 0)
                s_alpha[cur ^ 1][j >> 1] =
                    bf2_u32(__floats2bfloat162_rn(o, op));
        }
        __syncthreads();

        e_cur = e_next;
    }

    if (tid == 0) out[b] = ll;   // T_LEN % 8 == 0 -> last step renormalized
}

// ---------------------------------------------------------------------------
extern "C" void kernel_launch(void* const* d_in, const int* in_sizes, int n_in,
                              void* d_out, int out_size) {
    const float* inputs = nullptr;
    const float* A      = nullptr;
    const float* Bm     = nullptr;
    const float* Ivec   = nullptr;
    for (int i = 0; i < n_in; ++i) {
        switch (in_sizes[i]) {
            case NBATCH * T_LEN * E_DIM: inputs = (const float*)d_in[i]; break;
            case S_REAL * S_REAL:        A      = (const float*)d_in[i]; break;
            case S_REAL * E_DIM:         Bm     = (const float*)d_in[i]; break;
            case S_REAL:                 Ivec   = (const float*)d_in[i]; break;
            default: break;
        }
    }
    if (!inputs) inputs = (const float*)d_in[0];
    if (!A)      A      = (const float*)d_in[1];
    if (!Bm)     Bm     = (const float*)d_in[2];
    if (!Ivec)   Ivec   = (const float*)d_in[3];
    float* out = (float*)d_out;

    dim3 ggrid(SP / 64, (NBATCH * T_LEN) / 64);   // (5, 2048)
    prep_gemm_kernel<<<ggrid, 256>>>(inputs, Bm, A);

    scan_kernel<<<NBATCH, SCAN_THREADS>>>(Ivec, out);
    (void)out_size;
}

// round 7
// speedup vs baseline: 1.0250x; 1.0250x over previous
#include <cuda_runtime.h>
#include <cuda_bf16.h>
#include <stdint.h>

#define S_REAL   308
#define SP       320     // padded state count
#define E_DIM    126
#define T_LEN    4096
#define NBATCH   32
#define NIP      160     // SP/2 pair-words of alpha
#define SCAN_THREADS 640

// Scratch (device globals — no allocation in kernel_launch)
__device__ __nv_bfloat16 g_emis[(size_t)NBATCH * T_LEN * SP];   // 80 MB
// A pair-words, thread-major: uint4 chunk q (kk=4q..4q+3) for thread g lives
// at uint4 index q*640 + g  (warp reads 512B contiguous per chunk).
__device__ uint32_t g_apk2[640 * 80];                            // 200 KB

__device__ __forceinline__ __nv_bfloat162 u32_bf2(uint32_t v) {
    return *reinterpret_cast<__nv_bfloat162*>(&v);
}
__device__ __forceinline__ uint32_t bf2_u32(__nv_bfloat162 v) {
    return *reinterpret_cast<uint32_t*>(&v);
}

// ---------------------------------------------------------------------------
// Merged prep + emission GEMM. Blocks (bx==0, by<80) pack A*128 into g_apk2,
// then all blocks run the emission GEMM tile. 2 launches per call total.
// Thread g=2j+h of the scan handles i-pairs ip = h*80+kk, kk=0..79, output j.
// ---------------------------------------------------------------------------
__global__ void __launch_bounds__(256)
prep_gemm_kernel(const float* __restrict__ inp, const float* __restrict__ Bm,
                 const float* __restrict__ A) {
    const int tid = threadIdx.x;

    if (blockIdx.x == 0 && blockIdx.y < 80) {
        int gt = blockIdx.y * 256 + tid;
        for (int wi = gt; wi < 160 * SP; wi += 80 * 256) {
            int ip = wi / SP;
            int j  = wi - ip * SP;
            int i0 = 2 * ip, i1 = i0 + 1;
            float a0 = (i0 < S_REAL && j < S_REAL) ? A[i0 * S_REAL + j] * 128.f : 0.f;
            float a1 = (i1 < S_REAL && j < S_REAL) ? A[i1 * S_REAL + j] * 128.f : 0.f;
            uint32_t word = bf2_u32(__floats2bfloat162_rn(a0, a1));
            int h = ip / 80, kk = ip - h * 80;
            int g = 2 * j + h;
            g_apk2[((kk >> 2) * 640 + g) * 4 + (kk & 3)] = word;
        }
    }

    // ---------------- GEMM part (all blocks) ----------------
    __shared__ uint32_t sAp[64][16];
    __shared__ uint32_t sBp[16][64];

    const int tx = tid & 15;
    const int ty = tid >> 4;
    const int n0 = blockIdx.x * 64;
    const int m0 = blockIdx.y * 64;

    float acc[4][4];
#pragma unroll
    for (int u = 0; u < 4; ++u)
#pragma unroll
        for (int v = 0; v < 4; ++v) acc[u][v] = 0.f;

    const __nv_bfloat162 zero2 = __floats2bfloat162_rn(0.f, 0.f);

    for (int k0 = 0; k0 < 128; k0 += 32) {
#pragma unroll
        for (int r = 0; r < 4; ++r) {
            int lin = tid + r * 256;
            int mm = lin >> 4, kp = lin & 15;
            int k = k0 + 2 * kp;
            __nv_bfloat162 w = zero2;
            if (k < E_DIM) {
                float2 f = *reinterpret_cast<const float2*>(
                    &inp[(size_t)(m0 + mm) * E_DIM + k]);
                w = __floats2bfloat162_rn(f.x, f.y);
            }
            sAp[mm][kp] = bf2_u32(w);
        }
#pragma unroll
        for (int r = 0; r < 4; ++r) {
            int lin = tid + r * 256;
            int kp = lin >> 6, n = lin & 63;
            int k = k0 + 2 * kp;
            int nn = n0 + n;
            __nv_bfloat162 w = zero2;
            if (k < E_DIM && nn < S_REAL) {
                float2 f = *reinterpret_cast<const float2*>(
                    &Bm[(size_t)nn * E_DIM + k]);
                w = __floats2bfloat162_rn(f.x, f.y);
            }
            sBp[kp][n] = bf2_u32(w);
        }
        __syncthreads();

        __nv_bfloat162 acc2[4][4];
#pragma unroll
        for (int u = 0; u < 4; ++u)
#pragma unroll
            for (int v = 0; v < 4; ++v) acc2[u][v] = zero2;

#pragma unroll
        for (int kp = 0; kp < 16; ++kp) {
            uint4 bv = *reinterpret_cast<const uint4*>(&sBp[kp][tx * 4]);
            uint32_t a0 = sAp[ty * 4 + 0][kp];
            uint32_t a1 = sAp[ty * 4 + 1][kp];
            uint32_t a2 = sAp[ty * 4 + 2][kp];
            uint32_t a3 = sAp[ty * 4 + 3][kp];
            __nv_bfloat162 b0 = u32_bf2(bv.x), b1 = u32_bf2(bv.y);
            __nv_bfloat162 b2 = u32_bf2(bv.z), b3 = u32_bf2(bv.w);
            acc2[0][0] = __hfma2(u32_bf2(a0), b0, acc2[0][0]);
            acc2[0][1] = __hfma2(u32_bf2(a0), b1, acc2[0][1]);
            acc2[0][2] = __hfma2(u32_bf2(a0), b2, acc2[0][2]);
            acc2[0][3] = __hfma2(u32_bf2(a0), b3, acc2[0][3]);
            acc2[1][0] = __hfma2(u32_bf2(a1), b0, acc2[1][0]);
            acc2[1][1] = __hfma2(u32_bf2(a1), b1, acc2[1][1]);
            acc2[1][2] = __hfma2(u32_bf2(a1), b2, acc2[1][2]);
            acc2[1][3] = __hfma2(u32_bf2(a1), b3, acc2[1][3]);
            acc2[2][0] = __hfma2(u32_bf2(a2), b0, acc2[2][0]);
            acc2[2][1] = __hfma2(u32_bf2(a2), b1, acc2[2][1]);
            acc2[2][2] = __hfma2(u32_bf2(a2), b2, acc2[2][2]);
            acc2[2][3] = __hfma2(u32_bf2(a2), b3, acc2[2][3]);
            acc2[3][0] = __hfma2(u32_bf2(a3), b0, acc2[3][0]);
            acc2[3][1] = __hfma2(u32_bf2(a3), b1, acc2[3][1]);
            acc2[3][2] = __hfma2(u32_bf2(a3), b2, acc2[3][2]);
            acc2[3][3] = __hfma2(u32_bf2(a3), b3, acc2[3][3]);
        }
#pragma unroll
        for (int u = 0; u < 4; ++u)
#pragma unroll
            for (int v = 0; v < 4; ++v) {
                float2 p = __bfloat1622float2(acc2[u][v]);
                acc[u][v] += p.x + p.y;
            }
        __syncthreads();
    }
#pragma unroll
    for (int u = 0; u < 4; ++u) {
        int m = m0 + ty * 4 + u;
        size_t base = (size_t)m * SP + n0 + tx * 4;
#pragma unroll
        for (int v = 0; v < 4; v += 2) {
            __nv_bfloat162 p = __floats2bfloat162_rn(acc[u][v], acc[u][v + 1]);
            *reinterpret_cast<uint32_t*>(&g_emis[base + v]) = bf2_u32(p);
        }
    }
}

// ---------------------------------------------------------------------------
// Scan: one CTA per batch, 640 threads. Thread g: j = g>>1, h = g&1; computes
// sum over its 80 i-pairs (ip = h*80..h*80+79) of A[i][j]*alpha[i] in bf16x2,
// lane-pair combined with shfl_xor(1). 48 A-words register-resident, 32
// streamed in two 4xLDG.128 waves. One __syncthreads per step. Alpha (x128
// folded into A) renormalized every 16 steps; ll corrected by 4095*log(128).
// ---------------------------------------------------------------------------
__global__ void __launch_bounds__(SCAN_THREADS, 1)
scan_kernel(const float* __restrict__ Ivec, float* __restrict__ out) {
    __shared__ uint32_t s_alpha[2][NIP];   // bf16 alpha pairs, double-buffered
    __shared__ float    s_w[20];
    __shared__ float    s_inv;

    const int b    = blockIdx.x;
    const int tid  = threadIdx.x;
    const int g    = tid;
    const int j    = g >> 1;
    const int h    = g & 1;
    const int wrp  = tid >> 5;
    const int lane = tid & 31;

    const __nv_bfloat16* erow = g_emis + (size_t)b * T_LEN * SP;
    const uint4* As = reinterpret_cast<const uint4*>(g_apk2) + g;

    // register-resident A: kk 0..47 (12 uint4)
    uint4 rA[12];
#pragma unroll
    for (int r = 0; r < 12; ++r) rA[r] = As[r * 640];

    // t = 0: alpha0 = I * e0 (unnormalized) into buffer 1 (t=1 reads buf 1)
    if (tid < NIP) {
        int j0 = 2 * tid, j1 = j0 + 1;
        float e0 = __bfloat162float(erow[j0]);
        float e1 = __bfloat162float(erow[j1]);
        float w0 = (j0 < S_REAL) ? Ivec[j0] : 0.f;
        float w1 = (j1 < S_REAL) ? Ivec[j1] : 0.f;
        s_alpha[1][tid] = bf2_u32(__floats2bfloat162_rn(w0 * e0, w1 * e1));
    }
    __syncthreads();

    float ll = 0.f;
    float e_cur = __bfloat162float(erow[(size_t)SP + j]);

    const __nv_bfloat162 zero2 = __floats2bfloat162_rn(0.f, 0.f);

    for (int t = 1; t < T_LEN; ++t) {
        const int cur = t & 1;
        float e_next = 0.f;
        if (t + 1 < T_LEN)
            e_next = __bfloat162float(erow[(size_t)(t + 1) * SP + j]);

        const uint4* al4 = reinterpret_cast<const uint4*>(s_alpha[cur]) + h * 20;

        __nv_bfloat162 accA = zero2, accB = zero2;

        // wave 1 of streamed A: kk 48..63
        uint4 sb[4];
#pragma unroll
        for (int r = 0; r < 4; ++r) sb[r] = As[(12 + r) * 640];

        // resident chunks: kk 0..47
#pragma unroll
        for (int c = 0; c < 3; ++c) {
            uint4 av[4];
#pragma unroll
            for (int q = 0; q < 4; ++q) av[q] = al4[c * 4 + q];
            const uint32_t* aw = reinterpret_cast<const uint32_t*>(av);
#pragma unroll
            for (int q = 0; q < 4; ++q) {
                uint4 wv = rA[c * 4 + q];
                __nv_bfloat162 x0 = u32_bf2(aw[q * 4 + 0]);
                __nv_bfloat162 x1 = u32_bf2(aw[q * 4 + 1]);
                __nv_bfloat162 x2 = u32_bf2(aw[q * 4 + 2]);
                __nv_bfloat162 x3 = u32_bf2(aw[q * 4 + 3]);
                if (q & 1) {
                    accB = __hfma2(u32_bf2(wv.x), x0, accB);
                    accB = __hfma2(u32_bf2(wv.y), x1, accB);
                    accB = __hfma2(u32_bf2(wv.z), x2, accB);
                    accB = __hfma2(u32_bf2(wv.w), x3, accB);
                } else {
                    accA = __hfma2(u32_bf2(wv.x), x0, accA);
                    accA = __hfma2(u32_bf2(wv.y), x1, accA);
                    accA = __hfma2(u32_bf2(wv.z), x2, accA);
                    accA = __hfma2(u32_bf2(wv.w), x3, accA);
                }
            }
        }

        // wave 2 of streamed A: kk 64..79 (issued before consuming wave 1)
        uint4 sc[4];
#pragma unroll
        for (int r = 0; r < 4; ++r) sc[r] = As[(16 + r) * 640];

        // chunk 3: kk 48..63 with sb
        {
            uint4 av[4];
#pragma unroll
            for (int q = 0; q < 4; ++q) av[q] = al4[12 + q];
            const uint32_t* aw = reinterpret_cast<const uint32_t*>(av);
#pragma unroll
            for (int q = 0; q < 4; ++q) {
                uint4 wv = sb[q];
                __nv_bfloat162 x0 = u32_bf2(aw[q * 4 + 0]);
                __nv_bfloat162 x1 = u32_bf2(aw[q * 4 + 1]);
                __nv_bfloat162 x2 = u32_bf2(aw[q * 4 + 2]);
                __nv_bfloat162 x3 = u32_bf2(aw[q * 4 + 3]);
                if (q & 1) {
                    accB = __hfma2(u32_bf2(wv.x), x0, accB);
                    accB = __hfma2(u32_bf2(wv.y), x1, accB);
                    accB = __hfma2(u32_bf2(wv.z), x2, accB);
                    accB = __hfma2(u32_bf2(wv.w), x3, accB);
                } else {
                    accA = __hfma2(u32_bf2(wv.x), x0, accA);
                    accA = __hfma2(u32_bf2(wv.y), x1, accA);
                    accA = __hfma2(u32_bf2(wv.z), x2, accA);
                    accA = __hfma2(u32_bf2(wv.w), x3, accA);
                }
            }
        }
        // chunk 4: kk 64..79 with sc
        {
            uint4 av[4];
#pragma unroll
            for (int q = 0; q < 4; ++q) av[q] = al4[16 + q];
            const uint32_t* aw = reinterpret_cast<const uint32_t*>(av);
#pragma unroll
            for (int q = 0; q < 4; ++q) {
                uint4 wv = sc[q];
                __nv_bfloat162 x0 = u32_bf2(aw[q * 4 + 0]);
                __nv_bfloat162 x1 = u32_bf2(aw[q * 4 + 1]);
                __nv_bfloat162 x2 = u32_bf2(aw[q * 4 + 2]);
                __nv_bfloat162 x3 = u32_bf2(aw[q * 4 + 3]);
                if (q & 1) {
                    accB = __hfma2(u32_bf2(wv.x), x0, accB);
                    accB = __hfma2(u32_bf2(wv.y), x1, accB);
                    accB = __hfma2(u32_bf2(wv.z), x2, accB);
                    accB = __hfma2(u32_bf2(wv.w), x3, accB);
                } else {
                    accA = __hfma2(u32_bf2(wv.x), x0, accA);
                    accA = __hfma2(u32_bf2(wv.y), x1, accA);
                    accA = __hfma2(u32_bf2(wv.z), x2, accA);
                    accA = __hfma2(u32_bf2(wv.w), x3, accA);
                }
            }
        }

        float2 pa = __bfloat1622float2(accA);
        float2 pb = __bfloat1622float2(accB);
        float f = (pa.x + pa.y) + (pb.x + pb.y);

        // combine lane pair (h=0 + h=1 halves of the i-sum), apply emission
        float o = (f + __shfl_xor_sync(0xffffffffu, f, 1)) * e_cur;

        if ((t & 15) == 15) {
            // renormalize: z = sum_j o (each j duplicated on a lane pair;
            // reducing over offsets {2,4,8,16} sums 16 distinct j per warp)
            float s = o;
            s += __shfl_xor_sync(0xffffffffu, s, 2);
            s += __shfl_xor_sync(0xffffffffu, s, 4);
            s += __shfl_xor_sync(0xffffffffu, s, 8);
            s += __shfl_xor_sync(0xffffffffu, s, 16);
            if (lane == 0) s_w[wrp] = s;
            __syncthreads();
            if (tid == 0) {
                float z = 0.f;
#pragma unroll
                for (int k = 0; k < 20; ++k) z += s_w[k];
                ll += logf(z);
                s_inv = 1.0f / z;
            }
            __syncthreads();
            o *= s_inv;
        }

        // pack pair (j even, j odd) = lanes l, l+2 at l%4==0; store next alpha
        float op = __shfl_down_sync(0xffffffffu, o, 2);
        if ((lane & 3) == 0)
            s_alpha[cur ^ 1][8 * wrp + (lane >> 2)] =
                bf2_u32(__floats2bfloat162_rn(o, op));
        __syncthreads();

        e_cur = e_next;
    }

    // each step carried an extra factor 128 (folded into A)
    if (tid == 0) out[b] = ll - 4095.0f * logf(128.0f);
}

// ---------------------------------------------------------------------------
extern "C" void kernel_launch(void* const* d_in, const int* in_sizes, int n_in,
                              void* d_out, int out_size) {
    const float* inputs = nullptr;
    const float* A      = nullptr;
    const float* Bm     = nullptr;
    const float* Ivec   = nullptr;
    for (int i = 0; i < n_in; ++i) {
        switch (in_sizes[i]) {
            case NBATCH * T_LEN * E_DIM: inputs = (const float*)d_in[i]; break;
            case S_REAL * S_REAL:        A      = (const float*)d_in[i]; break;
            case S_REAL * E_DIM:         Bm     = (const float*)d_in[i]; break;
            case S_REAL:                 Ivec   = (const float*)d_in[i]; break;
            default: break;
        }
    }
    if (!inputs) inputs = (const float*)d_in[0];
    if (!A)      A      = (const float*)d_in[1];
    if (!Bm)     Bm     = (const float*)d_in[2];
    if (!Ivec)   Ivec   = (const float*)d_in[3];
    float* out = (float*)d_out;

    dim3 ggrid(SP / 64, (NBATCH * T_LEN) / 64);   // (5, 2048)
    prep_gemm_kernel<<<ggrid, 256>>>(inputs, Bm, A);

    scan_kernel<<<NBATCH, SCAN_THREADS>>>(Ivec, out);
    (void)out_size;
}